// round 9
// baseline (speedup 1.0000x reference)
#include <cuda_runtime.h>
#include <cuda_bf16.h>
#include <cstdint>

#define S_LEN 2048
#define HID   512
#define IN_D  128
#define OUT_D 64
#define ALPHA 0.2f
#define NCS   8          // column-split CTAs per batch group
#define NGRP  16         // batch groups
#define NTHR  512

typedef unsigned long long ull;

// ---- dynamic smem layout (float offsets) ----
#define HSTG_OFF 0                        // [16 warps][4 b][32 k] = 2048
#define XSTG_OFF 2048                     // [16 warps][4 b][8 i]  = 512
#define RED_ROW  264
#define RED_OFF  2560                     // [16][264] = 4224
#define WIH_OFF  6784                     // packed Wih: 4096 ull = 8192 floats
#define WHO2_OFF 14976                    // own k-block of Who, [64 k][64 o] = 4096
#define HLOC_OFF 19072                    // [2][256] own h slice = 512
#define SMEM_FLOATS 19584
#define SMEM_BYTES  (SMEM_FLOATS * 4)     // 78336

// L2-exchanged state
__device__ float    g_hbuf[2][64 * HID];
__device__ unsigned g_flags[NGRP * 32];   // flags at [g*32 + cs]

// ---------------- packed f32x2 helpers ----------------
__device__ __forceinline__ ull fma2(ull a, ull b, ull c) {
    ull d;
    asm("fma.rn.f32x2 %0, %1, %2, %3;" : "=l"(d) : "l"(a), "l"(b), "l"(c));
    return d;
}
__device__ __forceinline__ ull pack2(float a, float b) {
    ull r;
    asm("mov.b64 %0, {%1, %2};" : "=l"(r) : "r"(__float_as_uint(a)), "r"(__float_as_uint(b)));
    return r;
}
__device__ __forceinline__ float lo2(ull v) { return __uint_as_float((unsigned)(v & 0xffffffffull)); }
__device__ __forceinline__ float hi2(ull v) { return __uint_as_float((unsigned)(v >> 32)); }
__device__ __forceinline__ float my_tanh(float v) {
    float e = __expf(2.0f * v);               // inf -> exactly +1, branch-free
    return 1.0f - __fdividef(2.0f, e + 1.0f);
}
__device__ __forceinline__ void rel_st(unsigned* p, unsigned v) {
    asm volatile("st.release.gpu.u32 [%0], %1;" :: "l"(p), "r"(v) : "memory");
}
__device__ __forceinline__ unsigned poll_min8(const unsigned* flags) {
    unsigned f0, f1, f2, f3, f4, f5, f6, f7;
    asm volatile("ld.acquire.gpu.v4.u32 {%0,%1,%2,%3}, [%4];"
                 : "=r"(f0), "=r"(f1), "=r"(f2), "=r"(f3) : "l"(flags) : "memory");
    asm volatile("ld.acquire.gpu.v4.u32 {%0,%1,%2,%3}, [%4];"
                 : "=r"(f4), "=r"(f5), "=r"(f6), "=r"(f7) : "l"(flags + 4) : "memory");
    unsigned m = min(min(min(f0, f1), min(f2, f3)), min(min(f4, f5), min(f6, f7)));
    return m;
}

__global__ void rnn_init_kernel() {   // <<<64, 512>>>
    int i = blockIdx.x * 512 + threadIdx.x;
    if (i < NGRP * 32) g_flags[i] = 0u;
    g_hbuf[0][i] = 0.0f;              // 64*512 = 32768 = 64*512 threads exactly
}

__global__ void __launch_bounds__(NTHR, 1)
rnn_v9_kernel(const float* __restrict__ x,     // [64][2048][128]
              const float* __restrict__ Wih,   // [128][512]
              const float* __restrict__ Wrec,  // [512][512]
              const float* __restrict__ Who,   // [512][64]
              float* __restrict__ out)         // [64][2048][64], pre-zeroed
{
    extern __shared__ float smem[];
    float* hstg  = smem + HSTG_OFF;   // warp-private h stage [w][b][32]
    float* xstg  = smem + XSTG_OFF;   // warp-private x stage [w][b][8]
    float* red   = smem + RED_OFF;    // [16][264]
    ull*   wih_s = (ull*)(smem + WIH_OFF);  // [16 ks][4 ip][64]
    float* who2  = smem + WHO2_OFF;   // own k-block [64 k][64 o]
    float* hloc  = smem + HLOC_OFF;   // [2][256] own h slice

    const int t    = threadIdx.x;
    const int warp = t >> 5, lane = t & 31;
    const int g    = blockIdx.x >> 3;      // batch group
    const int cs   = blockIdx.x & 7;       // column split

    // compute mapping: 32 n-groups of 2 cols, 16 k-splits of 32 k
    const int nj = t & 31;
    const int ks = warp;
    const int n0 = cs * 64 + nj * 2;
    const int k0 = ks * 32;
    const int i0 = ks * 8;
    unsigned* flags = &g_flags[g * 32];

    // ---- W_rec slice -> registers, k-pair packed ----
    ull wr[32];
#pragma unroll
    for (int kp = 0; kp < 16; kp++) {
        float2 we = *(const float2*)&Wrec[(k0 + 2 * kp)     * HID + n0];
        float2 wo = *(const float2*)&Wrec[(k0 + 2 * kp + 1) * HID + n0];
        wr[kp * 2 + 0] = pack2(we.x, wo.x);
        wr[kp * 2 + 1] = pack2(we.y, wo.y);
    }
    // ---- Wih slice -> packed smem ----
#pragma unroll
    for (int ip = 0; ip < 4; ip++) {
        float2 we = *(const float2*)&Wih[(i0 + 2 * ip)     * HID + n0];
        float2 wo = *(const float2*)&Wih[(i0 + 2 * ip + 1) * HID + n0];
        wih_s[(ks * 4 + ip) * 64 + nj * 2 + 0] = pack2(we.x, wo.x);
        wih_s[(ks * 4 + ip) * 64 + nj * 2 + 1] = pack2(we.y, wo.y);
    }
    // ---- own Who k-block: contiguous copy [64k][64o] ----
    for (int idx = t * 4; idx < 64 * 64; idx += NTHR * 4)
        *(float4*)&who2[idx] = *(const float4*)&Who[cs * 64 * OUT_D + idx];
    // hloc zero (both parities)
    if (t < 512) hloc[t & 511] = 0.0f;
    // warp stage: h0 = 0, x[0]
    {
        int b = lane >> 3, ii = lane & 7;
        *(float4*)&hstg[warp * 128 + lane * 4] = make_float4(0.f, 0.f, 0.f, 0.f);
        xstg[warp * 32 + lane] = x[((size_t)(g * 4 + b) * S_LEN + 0) * IN_D + i0 + ii];
    }
    __syncthreads();

#pragma unroll 1
    for (int s = 0; s < S_LEN; s++) {
        const int ph = s & 1, pn = ph ^ 1;

        // ---- GEMM: h@Wrec + x@Wih from warp-private stage ----
        ull acc[8];
#pragma unroll
        for (int q = 0; q < 8; q++) acc[q] = 0ull;
#pragma unroll
        for (int c = 0; c < 8; c++) {
#pragma unroll
            for (int b = 0; b < 4; b++) {
                ulonglong2 h2 = *(const ulonglong2*)&hstg[warp * 128 + b * 32 + c * 4];
                acc[b * 2 + 0] = fma2(h2.x, wr[(c * 2) * 2 + 0],     acc[b * 2 + 0]);
                acc[b * 2 + 1] = fma2(h2.x, wr[(c * 2) * 2 + 1],     acc[b * 2 + 1]);
                acc[b * 2 + 0] = fma2(h2.y, wr[(c * 2 + 1) * 2 + 0], acc[b * 2 + 0]);
                acc[b * 2 + 1] = fma2(h2.y, wr[(c * 2 + 1) * 2 + 1], acc[b * 2 + 1]);
            }
        }
#pragma unroll
        for (int ip = 0; ip < 4; ip++) {
            ulonglong2 wv = *(const ulonglong2*)&wih_s[(ks * 4 + ip) * 64 + nj * 2];
#pragma unroll
            for (int b = 0; b < 4; b++) {
                float2 xv = *(const float2*)&xstg[warp * 32 + b * 8 + 2 * ip];
                ull xp = pack2(xv.x, xv.y);
                acc[b * 2 + 0] = fma2(xp, wv.x, acc[b * 2 + 0]);
                acc[b * 2 + 1] = fma2(xp, wv.y, acc[b * 2 + 1]);
            }
        }
#pragma unroll
        for (int b = 0; b < 4; b++) {
            float2 v;
            v.x = lo2(acc[b * 2 + 0]) + hi2(acc[b * 2 + 0]);
            v.y = lo2(acc[b * 2 + 1]) + hi2(acc[b * 2 + 1]);
            *(float2*)&red[ks * RED_ROW + b * 64 + nj * 2] = v;
        }
        __syncthreads();                          // S1 (only full barrier)

        if (t < 256) {
            // ---- finalize: reduce 16 k-splits, tanh, publish ----
            const int ob = t >> 6;                // hloc index == t
            float pre = 0.0f;
#pragma unroll
            for (int r = 0; r < 16; r++) pre += red[r * RED_ROW + t];
            float hold = hloc[ph * 256 + t];
            float hnew = (1.0f - ALPHA) * hold + ALPHA * my_tanh(pre);
            g_hbuf[pn][(size_t)(g * 4 + ob) * HID + cs * 64 + (t & 63)] = hnew;
            hloc[pn * 256 + t] = hnew;
            asm volatile("bar.sync 1, 256;" ::: "memory");   // warps 0-7 only
            if (t == 0) rel_st(&flags[cs], (unsigned)(s + 1));
        } else if (s) {
            // ---- warps 8-15: partial readout of row s-1 over own 64 k ----
            const int w2 = warp - 8;
            const int b  = w2 & 3;
            const int o  = ((w2 >> 2) << 5) + lane;     // 0..63
            const float* hl = &hloc[ph * 256 + b * 64];
            float sum = 0.0f;
#pragma unroll
            for (int kk = 0; kk < 64; kk += 4) {
                float4 hv = *(const float4*)&hl[kk];
                sum += hv.x * who2[(kk + 0) * 64 + o];
                sum += hv.y * who2[(kk + 1) * 64 + o];
                sum += hv.z * who2[(kk + 2) * 64 + o];
                sum += hv.w * who2[(kk + 3) * 64 + o];
            }
            float* dst = &out[((size_t)(g * 4 + b) * S_LEN + (s - 1)) * OUT_D + o];
            asm volatile("red.global.add.f32 [%0], %1;" :: "l"(dst), "f"(sum) : "memory");
        }

        if (s + 1 < S_LEN) {
            // ---- poll peers, then warp-private stage of h_{s+1}, x_{s+1} ----
            const unsigned target = (unsigned)(s + 1);
            while (poll_min8(flags) < target) { }
            const int b = lane >> 3, ii = lane & 7;
            float4 hv = __ldcg((const float4*)&g_hbuf[pn][(size_t)(g * 4 + b) * HID + k0 + ii * 4]);
            *(float4*)&hstg[warp * 128 + b * 32 + ii * 4] = hv;
            xstg[warp * 32 + lane] =
                x[((size_t)(g * 4 + b) * S_LEN + (s + 1)) * IN_D + i0 + ii];
            __syncwarp();
        }
    }

    // ---- epilogue: readout row 2047 from hloc[0] (h_2048) ----
    __syncthreads();
    if (warp >= 8) {
        const int w2 = warp - 8;
        const int b  = w2 & 3;
        const int o  = ((w2 >> 2) << 5) + lane;
        const float* hl = &hloc[0 * 256 + b * 64];
        float sum = 0.0f;
#pragma unroll
        for (int kk = 0; kk < 64; kk += 4) {
            float4 hv = *(const float4*)&hl[kk];
            sum += hv.x * who2[(kk + 0) * 64 + o];
            sum += hv.y * who2[(kk + 1) * 64 + o];
            sum += hv.z * who2[(kk + 2) * 64 + o];
            sum += hv.w * who2[(kk + 3) * 64 + o];
        }
        float* dst = &out[((size_t)(g * 4 + b) * S_LEN + (S_LEN - 1)) * OUT_D + o];
        asm volatile("red.global.add.f32 [%0], %1;" :: "l"(dst), "f"(sum) : "memory");
    }
}

extern "C" void kernel_launch(void* const* d_in, const int* in_sizes, int n_in,
                              void* d_out, int out_size) {
    const float* x    = (const float*)d_in[0];
    const float* Wih  = (const float*)d_in[1];
    const float* Wrec = (const float*)d_in[2];
    const float* Who  = (const float*)d_in[3];
    float* out = (float*)d_out;

    cudaMemsetAsync(d_out, 0, (size_t)out_size * sizeof(float));
    rnn_init_kernel<<<64, 512>>>();
    cudaFuncSetAttribute(rnn_v9_kernel,
                         cudaFuncAttributeMaxDynamicSharedMemorySize, SMEM_BYTES);
    rnn_v9_kernel<<<NGRP * NCS, NTHR, SMEM_BYTES>>>(x, Wih, Wrec, Who, out);
}

// round 10
// speedup vs baseline: 2.0319x; 2.0319x over previous
#include <cuda_runtime.h>
#include <cuda_bf16.h>
#include <cstdint>

#define S_LEN 2048
#define HID   512
#define IN_D  128
#define OUT_D 64
#define ALPHA 0.2f
#define NCS   8          // column-split CTAs per batch group
#define NGRP  16         // batch groups
#define NTHR  512

typedef unsigned long long ull;

// ---- dynamic smem layout (float offsets) ----
#define H_ROW   520
#define H_BUF   (4 * H_ROW)                  // 2080
#define H_OFF   0                            // h[2][4][520]
#define X_OFF   (2 * H_BUF)                  // 4160 : x[2][512]
#define RED_ROW 264
#define RED_OFF (X_OFF + 2 * 512)            // 5184 : red[16][264]
#define WHO_ROW 520
#define WHO_OFF (RED_OFF + 16 * RED_ROW)     // 9408 : who[8][520]
#define WIH_OFF (WHO_OFF + 8 * WHO_ROW)      // 13568 : packed Wih, 4096 ull = 8192 floats
#define SMEM_FLOATS (WIH_OFF + 8192)         // 21760
#define SMEM_BYTES  (SMEM_FLOATS * 4)        // 87040

// L2-exchanged state
__device__ float    g_hbuf[2][64 * HID];
__device__ unsigned g_cnt[NGRP * 32];

// ---------------- packed f32x2 helpers ----------------
__device__ __forceinline__ ull fma2(ull a, ull b, ull c) {
    ull d;
    asm("fma.rn.f32x2 %0, %1, %2, %3;" : "=l"(d) : "l"(a), "l"(b), "l"(c));
    return d;
}
__device__ __forceinline__ ull pack2(float a, float b) {
    ull r;
    asm("mov.b64 %0, {%1, %2};" : "=l"(r) : "r"(__float_as_uint(a)), "r"(__float_as_uint(b)));
    return r;
}
__device__ __forceinline__ float lo2(ull v) { return __uint_as_float((unsigned)(v & 0xffffffffull)); }
__device__ __forceinline__ float hi2(ull v) { return __uint_as_float((unsigned)(v >> 32)); }
__device__ __forceinline__ float my_tanh(float v) {
    float e = __expf(2.0f * v);               // inf -> exactly +1, branch-free
    return 1.0f - __fdividef(2.0f, e + 1.0f);
}
__device__ __forceinline__ void rel_add1(unsigned* p) {
    asm volatile("red.release.gpu.add.u32 [%0], 1;" :: "l"(p) : "memory");
}
__device__ __forceinline__ unsigned acq_ld(const unsigned* p) {
    unsigned v;
    asm volatile("ld.acquire.gpu.u32 %0, [%1];" : "=r"(v) : "l"(p) : "memory");
    return v;
}

__global__ void rnn_init_kernel() {
    if (threadIdx.x < NGRP) g_cnt[threadIdx.x * 32] = 0u;
}

// 8-warp readout: warp w2 = warp-8 -> (b = w2&3, o0 = (w2>>2)*4)
// conflict-free 16B-stride LDS; out row srow gets h@Who for this CTA's 8-o slice.
__device__ __forceinline__ void do_readout8(const float* hbuf, const float* who,
                                            int w2, int lane, int g, int cs,
                                            int srow, float* __restrict__ out) {
    const int b  = w2 & 3;
    const int o0 = (w2 >> 2) * 4;
    ull a0 = 0, a1 = 0, a2 = 0, a3 = 0;
#pragma unroll
    for (int c = 0; c < 4; c++) {
        int kk = c * 128 + lane * 4;                   // 16B lane stride
        ulonglong2 h2 = *(const ulonglong2*)&hbuf[b * H_ROW + kk];
        ulonglong2 w0 = *(const ulonglong2*)&who[(o0 + 0) * WHO_ROW + kk];
        ulonglong2 w1 = *(const ulonglong2*)&who[(o0 + 1) * WHO_ROW + kk];
        ulonglong2 w2v = *(const ulonglong2*)&who[(o0 + 2) * WHO_ROW + kk];
        ulonglong2 w3 = *(const ulonglong2*)&who[(o0 + 3) * WHO_ROW + kk];
        a0 = fma2(h2.x, w0.x, a0);  a0 = fma2(h2.y, w0.y, a0);
        a1 = fma2(h2.x, w1.x, a1);  a1 = fma2(h2.y, w1.y, a1);
        a2 = fma2(h2.x, w2v.x, a2); a2 = fma2(h2.y, w2v.y, a2);
        a3 = fma2(h2.x, w3.x, a3);  a3 = fma2(h2.y, w3.y, a3);
    }
    float f0 = lo2(a0) + hi2(a0);
    float f1 = lo2(a1) + hi2(a1);
    float f2 = lo2(a2) + hi2(a2);
    float f3 = lo2(a3) + hi2(a3);
#pragma unroll
    for (int off = 16; off; off >>= 1) {
        f0 += __shfl_xor_sync(~0u, f0, off);
        f1 += __shfl_xor_sync(~0u, f1, off);
        f2 += __shfl_xor_sync(~0u, f2, off);
        f3 += __shfl_xor_sync(~0u, f3, off);
    }
    if (lane == 0) {
        size_t base = ((size_t)(g * 4 + b) * S_LEN + srow) * OUT_D + cs * 8 + o0;
        *(float4*)&out[base] = make_float4(f0, f1, f2, f3);   // 16B-aligned
    }
}

__global__ void __launch_bounds__(NTHR, 1)
rnn_v10_kernel(const float* __restrict__ x,     // [64][2048][128]
               const float* __restrict__ Wih,   // [128][512]
               const float* __restrict__ Wrec,  // [512][512]
               const float* __restrict__ Who,   // [512][64]
               float* __restrict__ out)         // [64][2048][64]
{
    extern __shared__ float smem[];
    float* h_s   = smem + H_OFF;     // [2][4][520]
    float* x_s   = smem + X_OFF;     // [2][512]
    float* red   = smem + RED_OFF;   // [16][264]
    float* who_s = smem + WHO_OFF;   // [8][520]
    ull*   wih_s = (ull*)(smem + WIH_OFF);  // [16 ks][4 ip][64]

    const int t    = threadIdx.x;
    const int warp = t >> 5, lane = t & 31;
    const int g    = blockIdx.x >> 3;      // batch group
    const int cs   = blockIdx.x & 7;       // column split

    // compute mapping: 32 n-groups of 2 cols, 16 k-splits of 32 k
    const int nj = t & 31;
    const int ks = warp;
    const int n0 = cs * 64 + nj * 2;
    const int k0 = ks * 32;
    const int i0 = ks * 8;
    unsigned* cnt = &g_cnt[g * 32];

    // ---- W_rec slice -> registers, k-pair packed ----
    ull wr[32];
#pragma unroll
    for (int kp = 0; kp < 16; kp++) {
        float2 we = *(const float2*)&Wrec[(k0 + 2 * kp)     * HID + n0];
        float2 wo = *(const float2*)&Wrec[(k0 + 2 * kp + 1) * HID + n0];
        wr[kp * 2 + 0] = pack2(we.x, wo.x);
        wr[kp * 2 + 1] = pack2(we.y, wo.y);
    }
    // ---- Wih slice -> packed smem ----
#pragma unroll
    for (int ip = 0; ip < 4; ip++) {
        float2 we = *(const float2*)&Wih[(i0 + 2 * ip)     * HID + n0];
        float2 wo = *(const float2*)&Wih[(i0 + 2 * ip + 1) * HID + n0];
        wih_s[(ks * 4 + ip) * 64 + nj * 2 + 0] = pack2(we.x, wo.x);
        wih_s[(ks * 4 + ip) * 64 + nj * 2 + 1] = pack2(we.y, wo.y);
    }
    // Who o-slice transposed [o][k]
    for (int idx = t; idx < 8 * 512; idx += NTHR) {
        int ol = idx >> 9, k = idx & 511;
        who_s[ol * WHO_ROW + k] = Who[k * OUT_D + cs * 8 + ol];
    }
    // h0 = 0 in buffer 0; stage x[s=0] (threads 0-255)
    for (int idx = t; idx < H_BUF; idx += NTHR) h_s[idx] = 0.0f;
    if (t < 256) {
        int row = t >> 6, c2 = (t & 63) * 2;
        *(float2*)&x_s[row * 128 + c2] =
            *(const float2*)&x[((size_t)(g * 4 + row) * S_LEN) * IN_D + c2];
    }
    __syncthreads();

#pragma unroll 1
    for (int s = 0; s < S_LEN; s++) {
        const int ph = s & 1, pn = ph ^ 1;
        const float* hb = h_s + ph * H_BUF;
        const float* xb = x_s + ph * 512;

        // warps 0-7: prefetch next x early (LDG latency hidden under GEMM)
        float2 xn = make_float2(0.0f, 0.0f);
        const int xrow = t >> 6, xc2 = (t & 63) * 2;
        if (t < 256 && s + 1 < S_LEN)
            xn = *(const float2*)&x[((size_t)(g * 4 + xrow) * S_LEN + (s + 1)) * IN_D + xc2];

        // ---- GEMM: h@Wrec + x@Wih (all 16 warps) ----
        ull acc[8];
#pragma unroll
        for (int q = 0; q < 8; q++) acc[q] = 0ull;
#pragma unroll
        for (int c = 0; c < 8; c++) {
            int kk = k0 + c * 4;
#pragma unroll
            for (int b = 0; b < 4; b++) {
                ulonglong2 h2 = *(const ulonglong2*)&hb[b * H_ROW + kk];  // broadcast
                acc[b * 2 + 0] = fma2(h2.x, wr[(c * 2) * 2 + 0],     acc[b * 2 + 0]);
                acc[b * 2 + 1] = fma2(h2.x, wr[(c * 2) * 2 + 1],     acc[b * 2 + 1]);
                acc[b * 2 + 0] = fma2(h2.y, wr[(c * 2 + 1) * 2 + 0], acc[b * 2 + 0]);
                acc[b * 2 + 1] = fma2(h2.y, wr[(c * 2 + 1) * 2 + 1], acc[b * 2 + 1]);
            }
        }
#pragma unroll
        for (int ip = 0; ip < 4; ip++) {
            ulonglong2 wv = *(const ulonglong2*)&wih_s[(ks * 4 + ip) * 64 + nj * 2];
#pragma unroll
            for (int b = 0; b < 4; b++) {
                float2 xv = *(const float2*)&xb[b * 128 + i0 + 2 * ip];   // broadcast
                ull xp = pack2(xv.x, xv.y);
                acc[b * 2 + 0] = fma2(xp, wv.x, acc[b * 2 + 0]);
                acc[b * 2 + 1] = fma2(xp, wv.y, acc[b * 2 + 1]);
            }
        }
#pragma unroll
        for (int b = 0; b < 4; b++) {
            float2 v;
            v.x = lo2(acc[b * 2 + 0]) + hi2(acc[b * 2 + 0]);
            v.y = lo2(acc[b * 2 + 1]) + hi2(acc[b * 2 + 1]);
            *(float2*)&red[ks * RED_ROW + b * 64 + nj * 2] = v;
        }

        if (warp < 8) {
            // ---- finalize path (critical) ----
            asm volatile("bar.sync 2, %0;" :: "n"(NTHR) : "memory");  // pairs with arrive below
            const int ob = t >> 6, oc = t & 63;
            float pre = 0.0f;
#pragma unroll
            for (int r = 0; r < 16; r++) pre += red[r * RED_ROW + t];
            float hold = hb[ob * H_ROW + cs * 64 + oc];
            float hnew = (1.0f - ALPHA) * hold + ALPHA * my_tanh(pre);
            g_hbuf[pn][(size_t)(g * 4 + ob) * HID + cs * 64 + oc] = hnew;
            asm volatile("bar.sync 1, 256;" ::: "memory");            // finalize warps only
            if (t == 0) rel_add1(cnt);                                // release

            // x stage (off critical path for peers; before poll for us)
            *(float2*)&x_s[pn * 512 + xrow * 128 + xc2] = xn;

            // poll peers, then stage full h_{s+1} (8KB over 256 threads)
            {
                unsigned target = 8u * (unsigned)(s + 1);
                while (acq_ld(cnt) < target) { }
            }
            {
                const float* g_h = g_hbuf[pn];
                int off = t * 8;
                float4 a  = __ldcg((const float4*)&g_h[(size_t)g * 4 * HID + off]);
                float4 b4 = __ldcg((const float4*)&g_h[(size_t)g * 4 * HID + off + 4]);
                int bb2 = off >> 9, kk2 = off & 511;
                float* hn = h_s + pn * H_BUF;
                *(float4*)&hn[bb2 * H_ROW + kk2]     = a;
                *(float4*)&hn[bb2 * H_ROW + kk2 + 4] = b4;
            }
        } else {
            // ---- readout path (shadowed) ----
            asm volatile("bar.arrive 2, %0;" :: "n"(NTHR) : "memory");
            if (s) do_readout8(hb, who_s, warp - 8, lane, g, cs, s - 1, out);
        }
        __syncthreads();                          // S3: staged h + x visible to all
    }

    // epilogue: h_2048 staged into buffer 0 at s=2047 -> out row 2047
    if (warp >= 8)
        do_readout8(h_s, who_s, warp - 8, lane, g, cs, S_LEN - 1, out);
}

extern "C" void kernel_launch(void* const* d_in, const int* in_sizes, int n_in,
                              void* d_out, int out_size) {
    const float* x    = (const float*)d_in[0];
    const float* Wih  = (const float*)d_in[1];
    const float* Wrec = (const float*)d_in[2];
    const float* Who  = (const float*)d_in[3];
    float* out = (float*)d_out;

    rnn_init_kernel<<<1, 32>>>();
    cudaFuncSetAttribute(rnn_v10_kernel,
                         cudaFuncAttributeMaxDynamicSharedMemorySize, SMEM_BYTES);
    rnn_v10_kernel<<<NGRP * NCS, NTHR, SMEM_BYTES>>>(x, Wih, Wrec, Who, out);
}

// round 11
// speedup vs baseline: 2.2273x; 1.0962x over previous
#include <cuda_runtime.h>
#include <cuda_bf16.h>
#include <cstdint>

#define S_LEN 2048
#define HID   512
#define IN_D  128
#define OUT_D 64
#define ALPHA 0.2f
#define NCS   8          // column-split CTAs per batch group
#define NGRP  16         // batch groups
#define NTHR  512
#define FLAG_STRIDE 32   // one flag per 128B line

typedef unsigned long long ull;

// ---- dynamic smem layout (float offsets) ----
#define HSTG_OFF 0                         // [16 warps][128]  warp-private h tile
#define XSTG_OFF 2048                      // [2][16][32]      warp-private x tile
#define RED_ROW  264
#define RED_OFF  3072                      // [16][264]
#define WIH_OFF  7296                      // packed Wih: 4096 ull = 8192 floats
#define WHO_OFF  15488                     // own Who k-block, k-major [64 k][64 o]
#define HLOC_OFF 19584                     // [2][256] own h slice
#define SMEM_FLOATS 20096
#define SMEM_BYTES  (SMEM_FLOATS * 4)      // 80384

// L2-exchanged state
__device__ float    g_hbuf[2][64 * HID];
__device__ unsigned g_flags[NGRP * NCS * FLAG_STRIDE];

// ---------------- packed f32x2 helpers ----------------
__device__ __forceinline__ ull fma2(ull a, ull b, ull c) {
    ull d;
    asm("fma.rn.f32x2 %0, %1, %2, %3;" : "=l"(d) : "l"(a), "l"(b), "l"(c));
    return d;
}
__device__ __forceinline__ ull pack2(float a, float b) {
    ull r;
    asm("mov.b64 %0, {%1, %2};" : "=l"(r) : "r"(__float_as_uint(a)), "r"(__float_as_uint(b)));
    return r;
}
__device__ __forceinline__ float lo2(ull v) { return __uint_as_float((unsigned)(v & 0xffffffffull)); }
__device__ __forceinline__ float hi2(ull v) { return __uint_as_float((unsigned)(v >> 32)); }
__device__ __forceinline__ float my_tanh(float v) {
    float e = __expf(2.0f * v);               // inf -> exactly +1, branch-free
    return 1.0f - __fdividef(2.0f, e + 1.0f);
}
__device__ __forceinline__ void rel_st(unsigned* p, unsigned v) {
    asm volatile("st.release.gpu.u32 [%0], %1;" :: "l"(p), "r"(v) : "memory");
}
__device__ __forceinline__ unsigned acq_ld(const unsigned* p) {
    unsigned v;
    asm volatile("ld.acquire.gpu.u32 %0, [%1];" : "=r"(v) : "l"(p) : "memory");
    return v;
}

__global__ void rnn_init_kernel() {     // <<<8, 512>>>
    int i = blockIdx.x * 512 + threadIdx.x;
    if (i < NGRP * NCS * FLAG_STRIDE) g_flags[i] = 0u;
}

__global__ void __launch_bounds__(NTHR, 1)
rnn_v11_kernel(const float* __restrict__ x,     // [64][2048][128]
               const float* __restrict__ Wih,   // [128][512]
               const float* __restrict__ Wrec,  // [512][512]
               const float* __restrict__ Who,   // [512][64]
               float* __restrict__ out)         // [64][2048][64], pre-zeroed
{
    extern __shared__ float smem[];
    float* hstg  = smem + HSTG_OFF;   // [16][128]: [w][b*32 + k]
    float* xstg  = smem + XSTG_OFF;   // [2][16][32]: [ph][w][b*8 + i]
    float* red   = smem + RED_OFF;    // [16][264]
    ull*   wih_s = (ull*)(smem + WIH_OFF);   // [16 ks][4 ip][64]
    float* who2  = smem + WHO_OFF;    // [64 k][64 o] (k-major, == Who block layout)
    float* hloc  = smem + HLOC_OFF;   // [2][256] own h slice

    const int t    = threadIdx.x;
    const int warp = t >> 5, lane = t & 31;
    const int g    = blockIdx.x >> 3;      // batch group
    const int cs   = blockIdx.x & 7;       // column split

    // compute mapping: 32 n-groups of 2 cols, 16 k-splits of 32 k
    const int nj = t & 31;
    const int ks = warp;
    const int n0 = cs * 64 + nj * 2;
    const int k0 = ks * 32;
    const int i0 = ks * 8;
    const int prod = ks >> 1;              // producer CTA of this warp's k-range
    unsigned* my_flag   = &g_flags[(g * NCS + cs) * FLAG_STRIDE];
    unsigned* prod_flag = &g_flags[(g * NCS + prod) * FLAG_STRIDE];

    // ---- W_rec slice -> registers, k-pair packed ----
    ull wr[32];
#pragma unroll
    for (int kp = 0; kp < 16; kp++) {
        float2 we = *(const float2*)&Wrec[(k0 + 2 * kp)     * HID + n0];
        float2 wo = *(const float2*)&Wrec[(k0 + 2 * kp + 1) * HID + n0];
        wr[kp * 2 + 0] = pack2(we.x, wo.x);
        wr[kp * 2 + 1] = pack2(we.y, wo.y);
    }
    // ---- Wih slice -> packed smem ----
#pragma unroll
    for (int ip = 0; ip < 4; ip++) {
        float2 we = *(const float2*)&Wih[(i0 + 2 * ip)     * HID + n0];
        float2 wo = *(const float2*)&Wih[(i0 + 2 * ip + 1) * HID + n0];
        wih_s[(ks * 4 + ip) * 64 + nj * 2 + 0] = pack2(we.x, wo.x);
        wih_s[(ks * 4 + ip) * 64 + nj * 2 + 1] = pack2(we.y, wo.y);
    }
    // ---- own Who k-block (contiguous) ----
    for (int idx = t * 4; idx < 64 * 64; idx += NTHR * 4)
        *(float4*)&who2[idx] = *(const float4*)&Who[cs * 64 * OUT_D + idx];
    // hloc zero (both parities)
    hloc[t & 511] = 0.0f;
    // warp-private stage: h0 = 0; x[s=0]
    const int bb = lane >> 3, ii = lane & 7;
    *(float4*)&hstg[warp * 128 + lane * 4] = make_float4(0.f, 0.f, 0.f, 0.f);
    xstg[warp * 32 + lane] = x[((size_t)(g * 4 + bb) * S_LEN + 0) * IN_D + i0 + ii];
    __syncthreads();

#pragma unroll 1
    for (int s = 0; s < S_LEN; s++) {
        const int ph = s & 1, pn = ph ^ 1;
        const float* hb = hstg + warp * 128;
        const float* xb = xstg + (ph * 16 + warp) * 32;

        // prefetch next x (warp-private tile, 1 float/lane)
        float xn = 0.0f;
        if (s + 1 < S_LEN)
            xn = x[((size_t)(g * 4 + bb) * S_LEN + (s + 1)) * IN_D + i0 + ii];

        // ---- GEMM: h@Wrec + x@Wih from warp-private stage ----
        ull acc[8];
#pragma unroll
        for (int q = 0; q < 8; q++) acc[q] = 0ull;
#pragma unroll
        for (int c = 0; c < 8; c++) {
#pragma unroll
            for (int b = 0; b < 4; b++) {
                ulonglong2 h2 = *(const ulonglong2*)&hb[b * 32 + c * 4];  // broadcast
                acc[b * 2 + 0] = fma2(h2.x, wr[(c * 2) * 2 + 0],     acc[b * 2 + 0]);
                acc[b * 2 + 1] = fma2(h2.x, wr[(c * 2) * 2 + 1],     acc[b * 2 + 1]);
                acc[b * 2 + 0] = fma2(h2.y, wr[(c * 2 + 1) * 2 + 0], acc[b * 2 + 0]);
                acc[b * 2 + 1] = fma2(h2.y, wr[(c * 2 + 1) * 2 + 1], acc[b * 2 + 1]);
            }
        }
#pragma unroll
        for (int ip = 0; ip < 4; ip++) {
            ulonglong2 wv = *(const ulonglong2*)&wih_s[(ks * 4 + ip) * 64 + nj * 2];
#pragma unroll
            for (int b = 0; b < 4; b++) {
                float2 xv = *(const float2*)&xb[b * 8 + 2 * ip];          // broadcast
                ull xp = pack2(xv.x, xv.y);
                acc[b * 2 + 0] = fma2(xp, wv.x, acc[b * 2 + 0]);
                acc[b * 2 + 1] = fma2(xp, wv.y, acc[b * 2 + 1]);
            }
        }
#pragma unroll
        for (int b = 0; b < 4; b++) {
            float2 v;
            v.x = lo2(acc[b * 2 + 0]) + hi2(acc[b * 2 + 0]);
            v.y = lo2(acc[b * 2 + 1]) + hi2(acc[b * 2 + 1]);
            *(float2*)&red[ks * RED_ROW + b * 64 + nj * 2] = v;
        }
        // stage prefetched x (warp-private, other parity buffer)
        xstg[(pn * 16 + warp) * 32 + lane] = xn;

        __syncthreads();                          // S1: red + hloc(prev) visible

        if (t < 256) {
            // ---- finalize (critical path) ----
            const int ob = t >> 6, oc = t & 63;
            float pre = 0.0f;
#pragma unroll
            for (int r = 0; r < 16; r++) pre += red[r * RED_ROW + t];
            float hold = hloc[ph * 256 + t];
            float hnew = (1.0f - ALPHA) * hold + ALPHA * my_tanh(pre);
            g_hbuf[pn][(size_t)(g * 4 + ob) * HID + cs * 64 + oc] = hnew;
            hloc[pn * 256 + t] = hnew;
            asm volatile("bar.sync 1, 256;" ::: "memory");   // finalize warps only
            if (t == 0) rel_st(my_flag, (unsigned)(s + 1));  // release
        } else if (s) {
            // ---- shadow path: partial readout of row s-1 over own 64 k ----
            const int w2 = warp - 8;
            const int b  = w2 & 3;
            const int o  = ((w2 >> 2) << 5) + lane;          // 0..63
            const float* hl = &hloc[ph * 256 + b * 64];
            float sum = 0.0f;
#pragma unroll
            for (int kk = 0; kk < 64; kk += 4) {
                float4 hv = *(const float4*)&hl[kk];         // broadcast
                sum += hv.x * who2[(kk + 0) * 64 + o];
                sum += hv.y * who2[(kk + 1) * 64 + o];
                sum += hv.z * who2[(kk + 2) * 64 + o];
                sum += hv.w * who2[(kk + 3) * 64 + o];
            }
            float* dst = &out[((size_t)(g * 4 + b) * S_LEN + (s - 1)) * OUT_D + o];
            asm volatile("red.global.add.f32 [%0], %1;" :: "l"(dst), "f"(sum) : "memory");
        }

        if (s + 1 < S_LEN) {
            // ---- per-warp: wait ONLY for own producer, stage own 512B tile ----
            while (acq_ld(prod_flag) <= (unsigned)s) { }
            float4 hv = __ldcg((const float4*)
                &g_hbuf[pn][(size_t)(g * 4 + bb) * HID + k0 + ii * 4]);
            *(float4*)&hstg[warp * 128 + lane * 4] = hv;
            __syncwarp();
        }
    }

    // ---- epilogue: readout row 2047 from hloc[0] (h_2048) ----
    __syncthreads();
    if (warp >= 8) {
        const int w2 = warp - 8;
        const int b  = w2 & 3;
        const int o  = ((w2 >> 2) << 5) + lane;
        const float* hl = &hloc[0 * 256 + b * 64];
        float sum = 0.0f;
#pragma unroll
        for (int kk = 0; kk < 64; kk += 4) {
            float4 hv = *(const float4*)&hl[kk];
            sum += hv.x * who2[(kk + 0) * 64 + o];
            sum += hv.y * who2[(kk + 1) * 64 + o];
            sum += hv.z * who2[(kk + 2) * 64 + o];
            sum += hv.w * who2[(kk + 3) * 64 + o];
        }
        float* dst = &out[((size_t)(g * 4 + b) * S_LEN + (S_LEN - 1)) * OUT_D + o];
        asm volatile("red.global.add.f32 [%0], %1;" :: "l"(dst), "f"(sum) : "memory");
    }
}

extern "C" void kernel_launch(void* const* d_in, const int* in_sizes, int n_in,
                              void* d_out, int out_size) {
    const float* x    = (const float*)d_in[0];
    const float* Wih  = (const float*)d_in[1];
    const float* Wrec = (const float*)d_in[2];
    const float* Who  = (const float*)d_in[3];
    float* out = (float*)d_out;

    cudaMemsetAsync(d_out, 0, (size_t)out_size * sizeof(float));
    rnn_init_kernel<<<8, 512>>>();
    cudaFuncSetAttribute(rnn_v11_kernel,
                         cudaFuncAttributeMaxDynamicSharedMemorySize, SMEM_BYTES);
    rnn_v11_kernel<<<NGRP * NCS, NTHR, SMEM_BYTES>>>(x, Wih, Wrec, Who, out);
}